// round 4
// baseline (speedup 1.0000x reference)
#include <cuda_runtime.h>
#include <cuda_fp8.h>
#include <cstdint>
#include <math.h>

#define NN 4096
#define DD 64
#define LL 16
#define NT 32            // NN / 128 tiles per dim
#define NTRI 528         // NT*(NT+1)/2 triangular tile pairs
#define SURV_CAP (1 << 20)
#define GATE 54.0f       // widened fp8-noise-safe gate (true cutoff 50)
#define SRS 80           // smem row stride bytes (64 data + 16 pad): conflict-free LDS.32

// ---------------- device scratch (static, no allocation) ----------------
__device__ float   g_xp[2][LL][NN][DD];          // packed fp32 [mat][l][i][d]
__device__ uint8_t g_x8[2][LL][NN][DD];          // packed e4m3 row-major
__device__ float   g_norm[2][LL][NN];            // squared norms (exact fp32)
__device__ float   g_r[2][LL][NN];               // row sums of K (init 1 = diag)
__device__ float   g_S[LL];                      // off-diag Sum Kx*Ky
__device__ int     g_scount;

struct Surv { int ml; int i; int j; };
__device__ Surv g_surv[SURV_CAP];

// ---------------- fp8 mma (portable sm_89+ path, no arch suffix) -------------
__device__ __forceinline__ void mma_e4m3(float* d, const uint32_t* a, uint32_t b0, uint32_t b1) {
    asm volatile("mma.sync.aligned.m16n8k32.row.col.f32.e4m3.e4m3.f32 "
                 "{%0,%1,%2,%3}, {%4,%5,%6,%7}, {%8,%9}, {%0,%1,%2,%3};"
                 : "+f"(d[0]), "+f"(d[1]), "+f"(d[2]), "+f"(d[3])
                 : "r"(a[0]), "r"(a[1]), "r"(a[2]), "r"(a[3]), "r"(b0), "r"(b1));
}

// ---------------- init ----------------
__global__ void init_kernel() {
    int idx = blockIdx.x * blockDim.x + threadIdx.x;
    if (idx < 2 * LL * NN) ((float*)g_r)[idx] = 1.0f;
    if (idx < LL) g_S[idx] = 0.0f;
    if (idx == 0) g_scount = 0;
}

// ---------------- pack: (N, D, L) -> fp32 + e4m3 row-major + norms -----------
__global__ void pack_kernel(const float* __restrict__ X, const float* __restrict__ Y) {
    __shared__ float buf[DD * LL];      // buf[d*16 + l]
    const int m = blockIdx.y;
    const int i = blockIdx.x;
    const int t = threadIdx.x;
    const float* src = (m == 0 ? X : Y) + (size_t)i * (DD * LL);

#pragma unroll
    for (int q = 0; q < 4; ++q) buf[t + q * 256] = src[t + q * 256];
    __syncthreads();

#pragma unroll
    for (int q = 0; q < 4; ++q) {
        int e = t + q * 256;
        int l = e >> 6;
        int d = e & 63;
        float v = buf[d * LL + l];
        g_xp[m][l][i][d] = v;
        g_x8[m][l][i][d] = __nv_cvt_float_to_fp8(v, __NV_SATFINITE, __NV_E4M3);
    }
    if (t < LL) {
        float s = 0.0f;
#pragma unroll
        for (int d = 0; d < DD; ++d) { float v = buf[d * LL + t]; s = fmaf(v, v, s); }
        g_norm[m][t][i] = s;
    }
}

// ---------------- main: 128x128x64 FP8 HMMA Gram + masked epilogue -----------
__global__ void __launch_bounds__(256) gram_kernel() {
    // decode triangular tile pair (it <= jt)
    int p = blockIdx.x, it = 0, rem = NT;
    while (p >= rem) { p -= rem; rem--; it++; }
    const int jt = it + p;
    const int l = blockIdx.y;
    const int m = blockIdx.z;
    const int i0 = it * 128, j0 = jt * 128;

    __shared__ __align__(16) uint8_t As[128 * SRS];
    __shared__ __align__(16) uint8_t Bs[128 * SRS];
    __shared__ float nI[128], nJ[128];

    const int t = threadIdx.x;
    const int w = t >> 5;
    const int lane = t & 31;
    const int wm = w >> 2;            // 0..1 -> 64-row band
    const int wn = w & 3;             // 0..3 -> 32-col band
    const int qr = lane >> 2;         // quad row 0..7
    const int qc = lane & 3;          // quad col 0..3

    // fill smem (global rows are 64B = 4 uint4)
    {
        const uint4* gA = (const uint4*)&g_x8[m][l][i0][0];
        const uint4* gB = (const uint4*)&g_x8[m][l][j0][0];
#pragma unroll
        for (int q = 0; q < 2; ++q) {
            int idx = t + q * 256;          // 512 chunks
            int row = idx >> 2, ch = idx & 3;
            *(uint4*)&As[row * SRS + ch * 16] = gA[idx];
            *(uint4*)&Bs[row * SRS + ch * 16] = gB[idx];
        }
        if (t < 128) nI[t] = g_norm[m][l][i0 + t];
        else         nJ[t - 128] = g_norm[m][l][j0 + t - 128];
    }
    __syncthreads();

    float acc[4][4][4];               // [m-frag][n-frag][reg]
#pragma unroll
    for (int a = 0; a < 4; ++a)
#pragma unroll
        for (int b = 0; b < 4; ++b)
#pragma unroll
            for (int r = 0; r < 4; ++r) acc[a][b][r] = 0.0f;

#pragma unroll
    for (int ks = 0; ks < 2; ++ks) {  // K=64 in 2 steps of 32
        const int ko = ks * 32;
        uint32_t af[4][4], bf[4][2];
#pragma unroll
        for (int mf = 0; mf < 4; ++mf) {
            const uint8_t* ab = &As[(wm * 64 + mf * 16 + qr) * SRS + qc * 4 + ko];
            af[mf][0] = *(const uint32_t*)(ab);
            af[mf][1] = *(const uint32_t*)(ab + 8 * SRS);
            af[mf][2] = *(const uint32_t*)(ab + 16);
            af[mf][3] = *(const uint32_t*)(ab + 8 * SRS + 16);
        }
#pragma unroll
        for (int nf = 0; nf < 4; ++nf) {
            const uint8_t* bb = &Bs[(wn * 32 + nf * 8 + qr) * SRS + qc * 4 + ko];
            bf[nf][0] = *(const uint32_t*)(bb);
            bf[nf][1] = *(const uint32_t*)(bb + 16);
        }
#pragma unroll
        for (int mf = 0; mf < 4; ++mf)
#pragma unroll
            for (int nf = 0; nf < 4; ++nf)
                mma_e4m3(acc[mf][nf], af[mf], bf[nf][0], bf[nf][1]);
    }

    // epilogue: conservative per-fragment mask, cold exact path
    float rmin[4], cmin[4];
#pragma unroll
    for (int mf = 0; mf < 4; ++mf)
        rmin[mf] = 0.5f * fminf(nI[wm * 64 + mf * 16 + qr], nI[wm * 64 + mf * 16 + qr + 8]);
#pragma unroll
    for (int nf = 0; nf < 4; ++nf)
        cmin[nf] = 0.5f * fminf(nJ[wn * 32 + nf * 8 + 2 * qc], nJ[wn * 32 + nf * 8 + 2 * qc + 1]);

    uint32_t mask = 0;
#pragma unroll
    for (int mf = 0; mf < 4; ++mf)
#pragma unroll
        for (int nf = 0; nf < 4; ++nf) {
            float mx = fmaxf(fmaxf(acc[mf][nf][0], acc[mf][nf][1]),
                             fmaxf(acc[mf][nf][2], acc[mf][nf][3]));
            // mx > 0.5(nImin+nJmin) - GATE/2  <=>  d2min_est < GATE
            if (mx > rmin[mf] + cmin[nf] - 0.5f * GATE) mask |= 1u << (mf * 4 + nf);
        }

    if (mask) {   // cold path: exact per-element gate + survivor append
#pragma unroll
        for (int mf = 0; mf < 4; ++mf)
#pragma unroll
            for (int nf = 0; nf < 4; ++nf) {
                if (!(mask & (1u << (mf * 4 + nf)))) continue;
#pragma unroll
                for (int r = 0; r < 4; ++r) {
                    const int li = wm * 64 + mf * 16 + qr + ((r >> 1) << 3);
                    const int lj = wn * 32 + nf * 8 + 2 * qc + (r & 1);
                    const int gi = i0 + li;
                    const int gj = j0 + lj;
                    float d2 = nI[li] + nJ[lj] - 2.0f * acc[mf][nf][r];
                    if (gj > gi && d2 < GATE) {
                        int s = atomicAdd(&g_scount, 1);
                        if (s < SURV_CAP) {
                            g_surv[s].ml = (l << 1) | m;
                            g_surv[s].i = gi; g_surv[s].j = gj;
                        }
                    }
                }
            }
    }
}

// ---------------- survivors: exact fp32 recompute + row sums + S -------------
__device__ __forceinline__ float dot64(const float* __restrict__ a, const float* __restrict__ b) {
    float s = 0.0f;
#pragma unroll
    for (int q = 0; q < 16; ++q) {
        float4 x = ((const float4*)a)[q];
        float4 y = ((const float4*)b)[q];
        s = fmaf(x.x, y.x, s); s = fmaf(x.y, y.y, s);
        s = fmaf(x.z, y.z, s); s = fmaf(x.w, y.w, s);
    }
    return s;
}

__global__ void surv_kernel() {
    int cnt = g_scount; if (cnt > SURV_CAP) cnt = SURV_CAP;
    for (int s = blockIdx.x * blockDim.x + threadIdx.x; s < cnt;
         s += gridDim.x * blockDim.x) {
        Surv v = g_surv[s];
        const int m = v.ml & 1;
        const int l = v.ml >> 1;
        const int om = m ^ 1;

        // exact own-matrix d2 (fp8 only gated the threshold)
        const float* bs = &g_xp[m][l][0][0];
        float d2s = g_norm[m][l][v.i] + g_norm[m][l][v.j]
                  - 2.0f * dot64(bs + (size_t)v.i * DD, bs + (size_t)v.j * DD);
        d2s = fmaxf(d2s, 0.0f);
        float val = __expf(-0.5f * d2s);
        atomicAdd(&g_r[m][l][v.i], val);
        atomicAdd(&g_r[m][l][v.j], val);

        // cross-matrix term for S
        const float* bo = &g_xp[om][l][0][0];
        float d2o = g_norm[om][l][v.i] + g_norm[om][l][v.j]
                  - 2.0f * dot64(bo + (size_t)v.i * DD, bo + (size_t)v.j * DD);
        d2o = fmaxf(d2o, 0.0f);
        // dedup: pair gated in BOTH matrices appears twice; x-side (m=0) owns it.
        // Overlap forces d2s+d2o < ~2*GATE => any mis-dedup term < exp(-25), negligible.
        if (m == 1 && d2o < GATE) continue;
        atomicAdd(&g_S[l], 2.0f * __expf(-0.5f * (d2s + d2o)));  // (i,j) and (j,i)
    }
}

// ---------------- finish: combine into HSIC sum ----------------
__global__ void finish_kernel(float* __restrict__ out) {
    __shared__ double sh0[256], sh1[256], sh2[256];
    const int t = threadIdx.x;
    double total = 0.0;
    const double n = (double)NN;

    for (int l = 0; l < LL; ++l) {
        const float* rx = &g_r[0][l][0];
        const float* ry = &g_r[1][l][0];
        double p = 0.0, sx = 0.0, sy = 0.0;
        for (int i = t; i < NN; i += 256) {
            double ax = (double)rx[i], ay = (double)ry[i];
            p += ax * ay; sx += ax; sy += ay;
        }
        sh0[t] = p; sh1[t] = sx; sh2[t] = sy;
        __syncthreads();
        for (int s = 128; s > 0; s >>= 1) {
            if (t < s) { sh0[t] += sh0[t + s]; sh1[t] += sh1[t + s]; sh2[t] += sh2[t + s]; }
            __syncthreads();
        }
        if (t == 0) {
            double S = n + (double)g_S[l];               // diagonal contributes n
            double num = S - 2.0 * sh0[0] / n + sh1[0] * sh2[0] / (n * n);
            total += num / ((n - 1.0) * (n - 1.0));
        }
        __syncthreads();
    }
    if (t == 0) out[0] = (float)total;
}

// ---------------- launch ----------------
extern "C" void kernel_launch(void* const* d_in, const int* in_sizes, int n_in,
                              void* d_out, int out_size) {
    const float* X = (const float*)d_in[0];
    const float* Y = (const float*)d_in[1];
    float* out = (float*)d_out;

    init_kernel<<<(2 * LL * NN + 255) / 256, 256>>>();
    pack_kernel<<<dim3(NN, 2), 256>>>(X, Y);
    gram_kernel<<<dim3(NTRI, LL, 2), 256>>>();
    surv_kernel<<<64, 256>>>();
    finish_kernel<<<1, 256>>>(out);
}

// round 5
// speedup vs baseline: 1.3963x; 1.3963x over previous
#include <cuda_runtime.h>
#include <cuda_bf16.h>
#include <cstdint>
#include <math.h>

#define NN 4096
#define DD 64
#define LL 16
#define NT 32            // NN / 128 tiles per dim
#define NTRI 528         // NT*(NT+1)/2 triangular tile pairs
#define SURV_CAP (1 << 20)
#define GATE 52.0f       // bf16-noise-safe gate (true cutoff 50, exp(-25) mass)
#define SMS 72           // padded smem row stride (bf16 elems): conflict-free ldmatrix

// ---------------- device scratch (static, no allocation) ----------------
__device__ float g_xp[2][LL][NN][DD];            // packed fp32 [mat][l][i][d]
__device__ __nv_bfloat16 g_xb[2][LL][NN][DD];    // packed bf16 row-major
__device__ float g_norm[2][LL][NN];              // squared norms (exact fp32)
__device__ float g_r[2][LL][NN];                 // row sums of K (init 1 = diag)
__device__ float g_S[LL];                        // off-diag Sum Kx*Ky
__device__ int   g_scount;

struct Surv { int ml; int i; int j; };
__device__ Surv g_surv[SURV_CAP];

// ---------------- warp MMA helpers (portable sm_80+ path) ----------------
__device__ __forceinline__ uint32_t smem_u32(const void* p) {
    uint32_t a;
    asm("{ .reg .u64 t; cvta.to.shared.u64 t, %1; cvt.u32.u64 %0, t; }"
        : "=r"(a) : "l"(p));
    return a;
}
__device__ __forceinline__ void ldsm_x4(uint32_t* r, uint32_t addr) {
    asm volatile("ldmatrix.sync.aligned.m8n8.x4.shared.b16 {%0,%1,%2,%3}, [%4];"
                 : "=r"(r[0]), "=r"(r[1]), "=r"(r[2]), "=r"(r[3]) : "r"(addr));
}
__device__ __forceinline__ void mma16816(float* d, const uint32_t* a, uint32_t b0, uint32_t b1) {
    asm volatile("mma.sync.aligned.m16n8k16.row.col.f32.bf16.bf16.f32 "
                 "{%0,%1,%2,%3}, {%4,%5,%6,%7}, {%8,%9}, {%0,%1,%2,%3};"
                 : "+f"(d[0]), "+f"(d[1]), "+f"(d[2]), "+f"(d[3])
                 : "r"(a[0]), "r"(a[1]), "r"(a[2]), "r"(a[3]), "r"(b0), "r"(b1));
}

// ---------------- init ----------------
__global__ void init_kernel() {
    int idx = blockIdx.x * blockDim.x + threadIdx.x;
    if (idx < 2 * LL * NN) ((float*)g_r)[idx] = 1.0f;
    if (idx < LL) g_S[idx] = 0.0f;
    if (idx == 0) g_scount = 0;
}

// ---------------- pack: (N, D, L) -> fp32 + bf16 row-major + norms ----------
__global__ void pack_kernel(const float* __restrict__ X, const float* __restrict__ Y) {
    __shared__ float buf[DD * LL];      // buf[d*16 + l]
    const int m = blockIdx.y;
    const int i = blockIdx.x;
    const int t = threadIdx.x;
    const float* src = (m == 0 ? X : Y) + (size_t)i * (DD * LL);

#pragma unroll
    for (int q = 0; q < 4; ++q) buf[t + q * 256] = src[t + q * 256];
    __syncthreads();

#pragma unroll
    for (int q = 0; q < 4; ++q) {
        int e = t + q * 256;
        int l = e >> 6;
        int d = e & 63;
        float v = buf[d * LL + l];
        g_xp[m][l][i][d] = v;
        g_xb[m][l][i][d] = __float2bfloat16_rn(v);
    }
    if (t < LL) {
        float s = 0.0f;
#pragma unroll
        for (int d = 0; d < DD; ++d) { float v = buf[d * LL + t]; s = fmaf(v, v, s); }
        g_norm[m][t][i] = s;
    }
}

// ---------------- main: 128x128x64 HMMA Gram + masked epilogue ---------------
__global__ void __launch_bounds__(256, 2) gram_kernel() {
    // decode triangular tile pair (it <= jt)
    int p = blockIdx.x, it = 0, rem = NT;
    while (p >= rem) { p -= rem; rem--; it++; }
    const int jt = it + p;
    const int l = blockIdx.y;
    const int m = blockIdx.z;
    const int i0 = it * 128, j0 = jt * 128;

    __shared__ __align__(16) __nv_bfloat16 As[128 * SMS];
    __shared__ __align__(16) __nv_bfloat16 Bs[128 * SMS];
    __shared__ float nI[128], nJ[128];

    const int t = threadIdx.x;
    const int w = t >> 5;
    const int lane = t & 31;
    const int wm = w >> 2;            // 0..1  -> 64-row band
    const int wn = w & 3;             // 0..3  -> 32-col band
    const int qrow = lane >> 2;       // 0..7
    const int qc2 = (lane & 3) * 2;   // 0,2,4,6

    // fill smem tiles (row-major 64 -> padded 72)
    {
        const uint4* gA = (const uint4*)&g_xb[m][l][i0][0];   // 1024 chunks
        const uint4* gB = (const uint4*)&g_xb[m][l][j0][0];
#pragma unroll
        for (int q = 0; q < 4; ++q) {
            int idx = t + q * 256;
            int row = idx >> 3, c16 = idx & 7;
            *(uint4*)&As[row * SMS + c16 * 8] = gA[idx];
            *(uint4*)&Bs[row * SMS + c16 * 8] = gB[idx];
        }
        if (t < 128) nI[t] = g_norm[m][l][i0 + t];
        else         nJ[t - 128] = g_norm[m][l][j0 + t - 128];
    }
    __syncthreads();

    float acc[4][4][4];               // [m-frag][n8-frag][reg]
#pragma unroll
    for (int a = 0; a < 4; ++a)
#pragma unroll
        for (int b = 0; b < 4; ++b)
#pragma unroll
            for (int r = 0; r < 4; ++r) acc[a][b][r] = 0.0f;

    const int lrow = lane & 15;       // ldmatrix row select
    const int lcol = (lane >> 4) * 8; // ldmatrix col select (elements)

    const uint32_t aBase = smem_u32(As);
    const uint32_t bBase = smem_u32(Bs);

#pragma unroll
    for (int ks = 0; ks < 4; ++ks) {
        const int kc = ks * 16;
        uint32_t af[4][4], bf[2][4];
#pragma unroll
        for (int mf = 0; mf < 4; ++mf)
            ldsm_x4(af[mf], aBase + ((wm * 64 + mf * 16 + lrow) * SMS + kc + lcol) * 2);
#pragma unroll
        for (int nb = 0; nb < 2; ++nb)
            ldsm_x4(bf[nb], bBase + ((wn * 32 + nb * 16 + lrow) * SMS + kc + lcol) * 2);
#pragma unroll
        for (int mf = 0; mf < 4; ++mf)
#pragma unroll
            for (int j = 0; j < 4; ++j) {
                const int nb = j >> 1, hi = j & 1;
                mma16816(acc[mf][j], af[mf], bf[nb][hi], bf[nb][2 + hi]);
            }
    }

    // ---- epilogue: conservative per-fragment mask, exact path only if hit ----
    float rmin[4], cmin[4];
#pragma unroll
    for (int mf = 0; mf < 4; ++mf)
        rmin[mf] = 0.5f * fminf(nI[wm * 64 + mf * 16 + qrow],
                                nI[wm * 64 + mf * 16 + qrow + 8]);
#pragma unroll
    for (int j = 0; j < 4; ++j)
        cmin[j] = 0.5f * fminf(nJ[wn * 32 + j * 8 + qc2],
                               nJ[wn * 32 + j * 8 + qc2 + 1]);

    uint32_t mask = 0;
#pragma unroll
    for (int mf = 0; mf < 4; ++mf)
#pragma unroll
        for (int j = 0; j < 4; ++j) {
            float mx = fmaxf(fmaxf(acc[mf][j][0], acc[mf][j][1]),
                             fmaxf(acc[mf][j][2], acc[mf][j][3]));
            // mx > 0.5*(nImin+nJmin) - GATE/2  <=>  min possible d2 < GATE
            if (mx > rmin[mf] + cmin[j] - 0.5f * GATE) mask |= 1u << (mf * 4 + j);
        }

    if (mask) {   // cold path: exact per-element gate + survivor append
#pragma unroll
        for (int mf = 0; mf < 4; ++mf) {
#pragma unroll
            for (int j = 0; j < 4; ++j) {
                if (!(mask & (1u << (mf * 4 + j)))) continue;
#pragma unroll
                for (int r = 0; r < 4; ++r) {
                    const int li = wm * 64 + mf * 16 + qrow + ((r >> 1) << 3);
                    const int lj = wn * 32 + j * 8 + qc2 + (r & 1);
                    const int gi = i0 + li;
                    const int gj = j0 + lj;
                    float d2 = nI[li] + nJ[lj] - 2.0f * acc[mf][j][r];
                    if (gj > gi && d2 < GATE) {
                        int s = atomicAdd(&g_scount, 1);
                        if (s < SURV_CAP) {
                            g_surv[s].ml = (l << 1) | m;
                            g_surv[s].i = gi; g_surv[s].j = gj;
                        }
                    }
                }
            }
        }
    }
}

// ---------------- survivors: exact fp32 recompute + row sums + S -------------
__device__ __forceinline__ float dot64(const float* __restrict__ a, const float* __restrict__ b) {
    float s = 0.0f;
#pragma unroll
    for (int q = 0; q < 16; ++q) {
        float4 x = ((const float4*)a)[q];
        float4 y = ((const float4*)b)[q];
        s = fmaf(x.x, y.x, s); s = fmaf(x.y, y.y, s);
        s = fmaf(x.z, y.z, s); s = fmaf(x.w, y.w, s);
    }
    return s;
}

__global__ void surv_kernel() {
    int cnt = g_scount; if (cnt > SURV_CAP) cnt = SURV_CAP;
    for (int s = blockIdx.x * blockDim.x + threadIdx.x; s < cnt;
         s += gridDim.x * blockDim.x) {
        Surv v = g_surv[s];
        const int m = v.ml & 1;
        const int l = v.ml >> 1;
        const int om = m ^ 1;

        // exact own-matrix d2 (bf16 only gated the threshold)
        const float* bs = &g_xp[m][l][0][0];
        float d2s = g_norm[m][l][v.i] + g_norm[m][l][v.j]
                  - 2.0f * dot64(bs + (size_t)v.i * DD, bs + (size_t)v.j * DD);
        d2s = fmaxf(d2s, 0.0f);
        float val = __expf(-0.5f * d2s);
        atomicAdd(&g_r[m][l][v.i], val);
        atomicAdd(&g_r[m][l][v.j], val);

        // cross-matrix term for S
        const float* bo = &g_xp[om][l][0][0];
        float d2o = g_norm[om][l][v.i] + g_norm[om][l][v.j]
                  - 2.0f * dot64(bo + (size_t)v.i * DD, bo + (size_t)v.j * DD);
        d2o = fmaxf(d2o, 0.0f);
        // dedup: pair gated in BOTH matrices appears twice; x-side (m=0) owns it.
        if (m == 1 && d2o < GATE) continue;
        atomicAdd(&g_S[l], 2.0f * __expf(-0.5f * (d2s + d2o)));  // (i,j) and (j,i)
    }
}

// ---------------- finish: combine into HSIC sum ----------------
__global__ void finish_kernel(float* __restrict__ out) {
    __shared__ double sh0[256], sh1[256], sh2[256];
    const int t = threadIdx.x;
    double total = 0.0;
    const double n = (double)NN;

    for (int l = 0; l < LL; ++l) {
        const float* rx = &g_r[0][l][0];
        const float* ry = &g_r[1][l][0];
        double p = 0.0, sx = 0.0, sy = 0.0;
        for (int i = t; i < NN; i += 256) {
            double ax = (double)rx[i], ay = (double)ry[i];
            p += ax * ay; sx += ax; sy += ay;
        }
        sh0[t] = p; sh1[t] = sx; sh2[t] = sy;
        __syncthreads();
        for (int s = 128; s > 0; s >>= 1) {
            if (t < s) { sh0[t] += sh0[t + s]; sh1[t] += sh1[t + s]; sh2[t] += sh2[t + s]; }
            __syncthreads();
        }
        if (t == 0) {
            double S = n + (double)g_S[l];               // diagonal contributes n
            double num = S - 2.0 * sh0[0] / n + sh1[0] * sh2[0] / (n * n);
            total += num / ((n - 1.0) * (n - 1.0));
        }
        __syncthreads();
    }
    if (t == 0) out[0] = (float)total;
}

// ---------------- launch ----------------
extern "C" void kernel_launch(void* const* d_in, const int* in_sizes, int n_in,
                              void* d_out, int out_size) {
    const float* X = (const float*)d_in[0];
    const float* Y = (const float*)d_in[1];
    float* out = (float*)d_out;

    init_kernel<<<(2 * LL * NN + 255) / 256, 256>>>();
    pack_kernel<<<dim3(NN, 2), 256>>>(X, Y);
    gram_kernel<<<dim3(NTRI, LL, 2), 256>>>();
    surv_kernel<<<64, 256>>>();
    finish_kernel<<<1, 256>>>(out);
}